// round 7
// baseline (speedup 1.0000x reference)
#include <cuda_runtime.h>
#include <cuda_bf16.h>
#include <math.h>

// Shapes (fixed by the problem)
#define NB   4
#define CIN  256
#define HH   64
#define WW   64
#define HW   4096
#define CM   64
#define EOUT 100
#define OUTC 256

typedef unsigned long long u64;

// ---- packed fp32x2 helpers (Blackwell FFMA2 via PTX) ----------------------
__device__ __forceinline__ u64 pack2(float lo, float hi) {
    u64 d; asm("mov.b64 %0,{%1,%2};" : "=l"(d) : "f"(lo), "f"(hi)); return d;
}
__device__ __forceinline__ u64 splat2(float v) {
    u64 d; asm("mov.b64 %0,{%1,%1};" : "=l"(d) : "f"(v)); return d;
}
__device__ __forceinline__ void fma2(u64& acc, u64 a, u64 b) {
    asm("fma.rn.f32x2 %0,%1,%2,%0;" : "+l"(acc) : "l"(a), "l"(b));
}
__device__ __forceinline__ float2 unpack2(u64 d) {
    float2 r; asm("mov.b64 {%0,%1},%2;" : "=f"(r.x), "=f"(r.y) : "l"(d)); return r;
}

// Scratch (device globals; allocation is forbidden)
__device__ float g_t[NB * CM * HW];     // 4 MB   down-conv output
__device__ float g_e[NB * EOUT * HW];   // 6.5 MB encoder logits
__device__ float g_z[NB * OUTC * HW];   // 16 MB  z = W_out @ x (pre-upsample!)

// ---------------------------------------------------------------------------
// 1x1 conv as GEMM, 4 contiguous pixels per thread.  Weights stored
// DUPLICATED in smem ([C][MTILE][2]) so LDS.128 yields two pre-splatted
// f32x2 weight operands; the x float4 halves are natural register pairs.
// Inner loop per c: 1 LDG.128 + MTILE/2 LDS.128 + 2*MTILE FFMA2 (no MOVs).
// ---------------------------------------------------------------------------
template<int MTILE>
__global__ void __launch_bounds__(256) gemm1x1_v(
        const float* __restrict__ X, const float* __restrict__ Wm,
        const float* __restrict__ bias, float* __restrict__ out,
        int C, int M) {
    __shared__ float sWt[256 * MTILE * 2];   // [C][MTILE][2] (dup)
    const int m0 = blockIdx.y * MTILE;
    for (int idx = threadIdx.x; idx < C * MTILE; idx += 256) {
        int c = idx / MTILE, m = idx % MTILE;
        float w = Wm[(m0 + m) * C + c];
        sWt[idx * 2] = w; sWt[idx * 2 + 1] = w;
    }
    __syncthreads();

    const int p0  = (blockIdx.x * 256 + threadIdx.x) * 4;  // 4 contiguous pixels
    const int n   = p0 >> 12;
    const int pix = p0 & 4095;
    const ulonglong2* xb = (const ulonglong2*)(X + (size_t)n * C * HW) + (pix >> 2);

    // acc[m][0] = (pix0,pix1), acc[m][1] = (pix2,pix3)
    u64 acc[MTILE][2];
#pragma unroll
    for (int m = 0; m < MTILE; m++) {
        u64 bp = splat2(bias ? bias[m0 + m] : 0.0f);
        acc[m][0] = bp; acc[m][1] = bp;
    }

    const ulonglong2* sW2 = (const ulonglong2*)sWt;   // [C][MTILE/2]
#pragma unroll 4
    for (int c = 0; c < C; c++) {
        ulonglong2 xv = xb[c * (HW / 4)];   // .x=(x0,x1) .y=(x2,x3)
#pragma unroll
        for (int j = 0; j < MTILE / 2; j++) {
            ulonglong2 wv = sW2[c * (MTILE / 2) + j];  // (w2j,w2j),(w2j+1,w2j+1)
            fma2(acc[2*j  ][0], xv.x, wv.x);
            fma2(acc[2*j  ][1], xv.y, wv.x);
            fma2(acc[2*j+1][0], xv.x, wv.y);
            fma2(acc[2*j+1][1], xv.y, wv.y);
        }
    }

    ulonglong2* ob = (ulonglong2*)(out + (size_t)n * M * HW) + (pix >> 2);
#pragma unroll
    for (int m = 0; m < MTILE; m++)
        ob[(m0 + m) * (HW / 4)] = make_ulonglong2(acc[m][0], acc[m][1]);
}

// ---------------------------------------------------------------------------
// 3x3 encoder conv  t[4,64,64,64] -> e[4,100,64,64], SAME padding.
// 16x32 tile, 2 output rows/thread.  sT stored DUPLICATED (float2(t,t)) so
// tap splats are LDS.64 loads, no MOVs: per tap 2 LDS.64 + 5 LDS.128 (bcast)
// + 20 FFMA2.
// ---------------------------------------------------------------------------
#define QC  20
#define ICC 8

__global__ void __launch_bounds__(256) enc_conv_kernel(
        const float* __restrict__ T, const float* __restrict__ Wenc,
        const float* __restrict__ benc, float* __restrict__ E) {
    __shared__ float2 sT[ICC * 18 * 34];  // 39.2 KB (dup)
    __shared__ float  sW[ICC * 9 * QC];   // [m][tap][q]

    const int wtile = blockIdx.x;
    const int n     = blockIdx.y >> 2;
    const int htile = blockIdx.y & 3;
    const int ch0   = blockIdx.z * QC;
    const int tid   = threadIdx.x;
    const int ty    = tid >> 5, tx = tid & 31;
    const int h0 = htile * 16 - 1, w0 = wtile * 32 - 1;

    u64 acc_t[QC / 2], acc_u[QC / 2];
#pragma unroll
    for (int qp = 0; qp < QC / 2; qp++) {
        u64 bp = pack2(benc[ch0 + 2 * qp], benc[ch0 + 2 * qp + 1]);
        acc_t[qp] = bp; acc_u[qp] = bp;
    }

    for (int icc = 0; icc < CM / ICC; icc++) {
        const int ic0 = icc * ICC;
        __syncthreads();
        for (int idx = tid; idx < ICC * 18 * 34; idx += 256) {
            int ch = idx / 612, rem = idx % 612;
            int r = rem / 34, col = rem % 34;
            int gr = h0 + r, gc = w0 + col;
            float v = 0.0f;
            if ((unsigned)gr < HH && (unsigned)gc < WW)
                v = T[((n * CM + ic0 + ch) * HH + gr) * WW + gc];
            sT[idx] = make_float2(v, v);
        }
        for (int idx = tid; idx < ICC * 9 * QC; idx += 256) {
            int m = idx / (9 * QC), rem = idx % (9 * QC);
            int tap = rem / QC, q = rem % QC;
            sW[idx] = Wenc[((ch0 + q) * CM + ic0 + m) * 9 + tap];
        }
        __syncthreads();

        for (int m = 0; m < ICC; m++) {
            const u64* tb = (const u64*)sT + m * 612 + ty * 34 + tx;
#pragma unroll
            for (int ki = 0; ki < 3; ki++) {
#pragma unroll
                for (int kj = 0; kj < 3; kj++) {
                    const int tap = ki * 3 + kj;
                    u64 at = tb[ki * 34 + kj];            // (t,t)
                    u64 au = tb[8 * 34 + ki * 34 + kj];   // (u,u)
                    const ulonglong2* wb =
                        (const ulonglong2*)(sW + (m * 9 + tap) * QC);
#pragma unroll
                    for (int g = 0; g < QC / 4; g++) {
                        ulonglong2 wv = wb[g];
                        fma2(acc_t[2 * g],     at, wv.x);
                        fma2(acc_t[2 * g + 1], at, wv.y);
                        fma2(acc_u[2 * g],     au, wv.x);
                        fma2(acc_u[2 * g + 1], au, wv.y);
                    }
                }
            }
        }
    }

    const int h = htile * 16 + ty, w = wtile * 32 + tx;
#pragma unroll
    for (int qp = 0; qp < QC / 2; qp++) {
        float2 vt = unpack2(acc_t[qp]);
        float2 vu = unpack2(acc_u[qp]);
        E[((n * EOUT + ch0 + 2*qp    ) * HH + h    ) * WW + w] = vt.x;
        E[((n * EOUT + ch0 + 2*qp + 1) * HH + h    ) * WW + w] = vt.y;
        E[((n * EOUT + ch0 + 2*qp    ) * HH + h + 8) * WW + w] = vu.x;
        E[((n * EOUT + ch0 + 2*qp + 1) * HH + h + 8) * WW + w] = vu.y;
    }
}

// ---------------------------------------------------------------------------
// Fused softmax + reassembly + pixel-shuffle + bias.
// Stages 8 channels per iteration (16 its instead of 32): half the barriers,
// double the compute per staged round-trip.
// ---------------------------------------------------------------------------
__global__ void __launch_bounds__(256) carafe_kernel(
        const float* __restrict__ E, const float* __restrict__ Z,
        const float* __restrict__ bout, float* __restrict__ out) {
    __shared__ float sZ[2][8 * 5 * 72];   // 2 buf x 8 ch x 5 rows x 72 cols

    const int nh = blockIdx.x;
    const int n  = nh >> 6;
    const int h  = nh & 63;
    const int chalf = blockIdx.y;
    const int tid   = threadIdx.x;
    const int w     = tid & 63;
    const int psel  = (tid >> 6) & 1;
    const int cslot = tid >> 7;

    const int p0 = 2 * psel;
    float kr[50];
    const float* eb = E + (size_t)n * EOUT * HW + h * WW + w;
#pragma unroll
    for (int k = 0; k < 25; k++) {
        kr[k * 2 + 0] = eb[(k * 4 + p0 + 0) * HW];
        kr[k * 2 + 1] = eb[(k * 4 + p0 + 1) * HW];
    }
#pragma unroll
    for (int pp = 0; pp < 2; pp++) {
        float mx = kr[pp];
#pragma unroll
        for (int k = 1; k < 25; k++) mx = fmaxf(mx, kr[k * 2 + pp]);
        float s = 0.0f;
#pragma unroll
        for (int k = 0; k < 25; k++) {
            float ex = __expf(kr[k * 2 + pp] - mx);
            kr[k * 2 + pp] = ex;
            s += ex;
        }
        float inv = 1.0f / s;
#pragma unroll
        for (int k = 0; k < 25; k++) kr[k * 2 + pp] *= inv;
    }

    const int lane64 = tid & 63;
    const int sch    = tid >> 6;   // 0..3
    const int hch    = tid >> 5;   // 0..3 when tid<128
    const int t2     = tid & 31;
    float2* op = (float2*)out;

    auto stage = [&](int it, int buf) {
        const int cb = chalf * 128 + it * 8;
        float4* sZ4 = (float4*)sZ[buf];
#pragma unroll
        for (int cp = 0; cp < 8; cp += 4) {
            const float4* zc = (const float4*)(Z +
                ((size_t)(n * OUTC + cb + cp + sch) * HH) * WW);
            int r = lane64 >> 4, g = lane64 & 15;
            int row = h - 2 + r;
            float4 v = make_float4(0.f, 0.f, 0.f, 0.f);
            if ((unsigned)row < HH) v = zc[row * 16 + g];
            sZ4[(cp + sch) * 90 + r * 18 + 1 + g] = v;
            if (lane64 < 16) {                 // r = 4 remainder
                int row2 = h + 2;
                float4 v2 = make_float4(0.f, 0.f, 0.f, 0.f);
                if ((unsigned)row2 < HH) v2 = zc[row2 * 16 + lane64];
                sZ4[(cp + sch) * 90 + 4 * 18 + 1 + lane64] = v2;
            }
            if (tid < 128 && t2 < 20) {        // halo {-2,-1,64,65}
                int rr = t2 >> 2, cc = t2 & 3;
                int hrow = h - 2 + rr;
                int wc = (cc < 2) ? cc - 2 : 62 + cc;
                float hv = 0.0f;
                if ((unsigned)hrow < HH && (unsigned)wc < WW)
                    hv = Z[((size_t)(n * OUTC + cb + cp + hch) * HH + hrow) * WW + wc];
                sZ[buf][(cp + hch) * 360 + rr * 72 + ((cc < 2) ? cc + 2 : 66 + cc)] = hv;
            }
        }
    };

    stage(0, 0);
    __syncthreads();

    for (int it = 0; it < 16; it++) {
        if (it < 15) stage(it + 1, (it + 1) & 1);

        const int cbase = chalf * 128 + it * 8;
        const int row = 2 * h + psel;
#pragma unroll
        for (int ch = 0; ch < 4; ch++) {
            const int c = cbase + cslot * 4 + ch;
            const float* zb = sZ[it & 1] + (cslot * 4 + ch) * 360 + (w + 2);
            float a0 = 0.f, a1 = 0.f;
#pragma unroll
            for (int ki = 0; ki < 5; ki++) {
#pragma unroll
                for (int kj = 0; kj < 5; kj++) {
                    int kk = ki * 5 + kj;
                    float z = zb[ki * 72 + kj];
                    a0 += z * kr[kk * 2 + 0];
                    a1 += z * kr[kk * 2 + 1];
                }
            }
            float b = __ldg(bout + c);
            op[((n * OUTC + c) * 128 + row) * 64 + w] = make_float2(a0 + b, a1 + b);
        }
        __syncthreads();
    }
}

// ---------------------------------------------------------------------------
extern "C" void kernel_launch(void* const* d_in, const int* in_sizes, int n_in,
                              void* d_out, int out_size) {
    const float* x  = (const float*)d_in[0];
    const float* Wd = (const float*)d_in[1];
    const float* bd = (const float*)d_in[2];
    const float* We = (const float*)d_in[3];
    const float* be = (const float*)d_in[4];
    const float* Wo = (const float*)d_in[5];
    const float* bo = (const float*)d_in[6];
    float* out = (float*)d_out;

    static float* gt = nullptr;
    static float* ge = nullptr;
    static float* gz = nullptr;
    static cudaStream_t s2;
    static cudaEvent_t ev_fork, ev_join;
    if (!gt) {
        cudaGetSymbolAddress((void**)&gt, g_t);
        cudaGetSymbolAddress((void**)&ge, g_e);
        cudaGetSymbolAddress((void**)&gz, g_z);
        cudaStreamCreateWithFlags(&s2, cudaStreamNonBlocking);
        cudaEventCreateWithFlags(&ev_fork, cudaEventDisableTiming);
        cudaEventCreateWithFlags(&ev_join, cudaEventDisableTiming);
    }

    // Fork: z = W_out @ x is independent of the t/e path -> run concurrently.
    cudaEventRecord(ev_fork, 0);
    cudaStreamWaitEvent(s2, ev_fork, 0);
    gemm1x1_v<16><<<dim3(16, 16), 256, 0, s2>>>(x, Wo, nullptr, gz, CIN, OUTC);
    cudaEventRecord(ev_join, s2);

    // Main path: t = W_down @ x + b ; e = conv3x3(t) + b
    gemm1x1_v<8><<<dim3(16, 8), 256>>>(x, Wd, bd, gt, CIN, CM);
    enc_conv_kernel<<<dim3(2, 16, 5), 256>>>(gt, We, be, ge);

    // Join, then fused reassembly.
    cudaStreamWaitEvent(0, ev_join, 0);
    carafe_kernel<<<dim3(256, 2), 256>>>(ge, gz, bo, out);
}

// round 8
// speedup vs baseline: 1.8661x; 1.8661x over previous
#include <cuda_runtime.h>
#include <cuda_bf16.h>
#include <math.h>

// Shapes (fixed by the problem)
#define NB   4
#define CIN  256
#define HH   64
#define WW   64
#define HW   4096
#define CM   64
#define EOUT 100
#define OUTC 256

typedef unsigned long long u64;

// ---- packed fp32x2 helpers (Blackwell FFMA2 via PTX) ----------------------
__device__ __forceinline__ u64 pack2(float lo, float hi) {
    u64 d; asm("mov.b64 %0,{%1,%2};" : "=l"(d) : "f"(lo), "f"(hi)); return d;
}
__device__ __forceinline__ u64 splat2(float v) {
    u64 d; asm("mov.b64 %0,{%1,%1};" : "=l"(d) : "f"(v)); return d;
}
__device__ __forceinline__ void fma2(u64& acc, u64 a, u64 b) {
    asm("fma.rn.f32x2 %0,%1,%2,%0;" : "+l"(acc) : "l"(a), "l"(b));
}
__device__ __forceinline__ float2 unpack2(u64 d) {
    float2 r; asm("mov.b64 {%0,%1},%2;" : "=f"(r.x), "=f"(r.y) : "l"(d)); return r;
}

// Scratch (device globals; allocation is forbidden)
__device__ float g_t[NB * CM * HW];     // 4 MB   down-conv output
__device__ float g_e[NB * EOUT * HW];   // 6.5 MB encoder logits
__device__ float g_z[NB * OUTC * HW];   // 16 MB  z = W_out @ x (pre-upsample!)

// ---------------------------------------------------------------------------
// 1x1 conv as GEMM (proven R5-measured version).  Weights transposed in smem
// ([C][MTILE], m contiguous) -> ulonglong2 LDS.128 yields pre-packed
// (w_m, w_m+1) f32x2 operands; pixel value splatted once per c.
// ---------------------------------------------------------------------------
template<int MTILE>
__global__ void __launch_bounds__(256) gemm1x1_v(
        const float* __restrict__ X, const float* __restrict__ Wm,
        const float* __restrict__ bias, float* __restrict__ out,
        int C, int M) {
    __shared__ float sWt[256 * MTILE];   // [C][MTILE]
    const int m0 = blockIdx.y * MTILE;
    for (int idx = threadIdx.x; idx < C * MTILE; idx += 256)
        sWt[idx] = Wm[(m0 + (idx % MTILE)) * C + (idx / MTILE)];
    __syncthreads();

    const int p0  = (blockIdx.x * 256 + threadIdx.x) * 4;  // 4 contiguous pixels
    const int n   = p0 >> 12;
    const int pix = p0 & 4095;
    const float4* xb = (const float4*)(X + (size_t)n * C * HW) + (pix >> 2);

    // acc2[mp][p] = (acc[2mp][pixel p], acc[2mp+1][pixel p])
    u64 acc2[MTILE / 2][4];
#pragma unroll
    for (int mp = 0; mp < MTILE / 2; mp++) {
        float b0 = bias ? bias[m0 + 2 * mp]     : 0.0f;
        float b1 = bias ? bias[m0 + 2 * mp + 1] : 0.0f;
        u64 bp = pack2(b0, b1);
#pragma unroll
        for (int p = 0; p < 4; p++) acc2[mp][p] = bp;
    }

    const ulonglong2* sW2 = (const ulonglong2*)sWt;   // [C][MTILE/4]
#pragma unroll 4
    for (int c = 0; c < C; c++) {
        float4 xv = xb[c * (HW / 4)];
        u64 sx0 = splat2(xv.x), sx1 = splat2(xv.y);
        u64 sx2 = splat2(xv.z), sx3 = splat2(xv.w);
#pragma unroll
        for (int j = 0; j < MTILE / 4; j++) {
            ulonglong2 wv = sW2[c * (MTILE / 4) + j];
            fma2(acc2[2*j][0], sx0, wv.x);
            fma2(acc2[2*j][1], sx1, wv.x);
            fma2(acc2[2*j][2], sx2, wv.x);
            fma2(acc2[2*j][3], sx3, wv.x);
            fma2(acc2[2*j+1][0], sx0, wv.y);
            fma2(acc2[2*j+1][1], sx1, wv.y);
            fma2(acc2[2*j+1][2], sx2, wv.y);
            fma2(acc2[2*j+1][3], sx3, wv.y);
        }
    }

    float4* ob = (float4*)(out + (size_t)n * M * HW) + (pix >> 2);
#pragma unroll
    for (int mp = 0; mp < MTILE / 2; mp++) {
        float2 q0 = unpack2(acc2[mp][0]), q1 = unpack2(acc2[mp][1]);
        float2 q2 = unpack2(acc2[mp][2]), q3 = unpack2(acc2[mp][3]);
        ob[(m0 + 2 * mp    ) * (HW / 4)] = make_float4(q0.x, q1.x, q2.x, q3.x);
        ob[(m0 + 2 * mp + 1) * (HW / 4)] = make_float4(q0.y, q1.y, q2.y, q3.y);
    }
}

// ---------------------------------------------------------------------------
// 3x3 encoder conv (proven R5-measured version).  16x32 tile, 2 output rows
// per thread, weights [m][tap][q] with q contiguous -> pre-packed pairs.
// ---------------------------------------------------------------------------
#define QC  20
#define ICC 8

__global__ void __launch_bounds__(256) enc_conv_kernel(
        const float* __restrict__ T, const float* __restrict__ Wenc,
        const float* __restrict__ benc, float* __restrict__ E) {
    __shared__ float sT[ICC * 18 * 34];   // 4896 floats
    __shared__ float sW[ICC * 9 * QC];    // 1440 floats: [m][tap][q]

    const int wtile = blockIdx.x;
    const int n     = blockIdx.y >> 2;
    const int htile = blockIdx.y & 3;
    const int ch0   = blockIdx.z * QC;
    const int tid   = threadIdx.x;
    const int ty    = tid >> 5, tx = tid & 31;
    const int h0 = htile * 16 - 1, w0 = wtile * 32 - 1;

    u64 acc_t[QC / 2], acc_u[QC / 2];
#pragma unroll
    for (int qp = 0; qp < QC / 2; qp++) {
        u64 bp = pack2(benc[ch0 + 2 * qp], benc[ch0 + 2 * qp + 1]);
        acc_t[qp] = bp; acc_u[qp] = bp;
    }

    for (int icc = 0; icc < CM / ICC; icc++) {
        const int ic0 = icc * ICC;
        __syncthreads();
        for (int idx = tid; idx < ICC * 18 * 34; idx += 256) {
            int ch = idx / 612, rem = idx % 612;
            int r = rem / 34, col = rem % 34;
            int gr = h0 + r, gc = w0 + col;
            float v = 0.0f;
            if ((unsigned)gr < HH && (unsigned)gc < WW)
                v = T[((n * CM + ic0 + ch) * HH + gr) * WW + gc];
            sT[idx] = v;
        }
        for (int idx = tid; idx < ICC * 9 * QC; idx += 256) {
            int m = idx / (9 * QC), rem = idx % (9 * QC);
            int tap = rem / QC, q = rem % QC;
            sW[idx] = Wenc[((ch0 + q) * CM + ic0 + m) * 9 + tap];
        }
        __syncthreads();

        for (int m = 0; m < ICC; m++) {
            const float* tb = sT + m * 612 + ty * 34 + tx;
            const float* ub = tb + 8 * 34;
#pragma unroll
            for (int ki = 0; ki < 3; ki++) {
#pragma unroll
                for (int kj = 0; kj < 3; kj++) {
                    const int tap = ki * 3 + kj;
                    u64 at = splat2(tb[ki * 34 + kj]);
                    u64 au = splat2(ub[ki * 34 + kj]);
                    const ulonglong2* wb =
                        (const ulonglong2*)(sW + (m * 9 + tap) * QC);
#pragma unroll
                    for (int g = 0; g < QC / 4; g++) {
                        ulonglong2 wv = wb[g];
                        fma2(acc_t[2 * g],     at, wv.x);
                        fma2(acc_t[2 * g + 1], at, wv.y);
                        fma2(acc_u[2 * g],     au, wv.x);
                        fma2(acc_u[2 * g + 1], au, wv.y);
                    }
                }
            }
        }
    }

    const int h = htile * 16 + ty, w = wtile * 32 + tx;
#pragma unroll
    for (int qp = 0; qp < QC / 2; qp++) {
        float2 vt = unpack2(acc_t[qp]);
        float2 vu = unpack2(acc_u[qp]);
        E[((n * EOUT + ch0 + 2*qp    ) * HH + h    ) * WW + w] = vt.x;
        E[((n * EOUT + ch0 + 2*qp + 1) * HH + h    ) * WW + w] = vt.y;
        E[((n * EOUT + ch0 + 2*qp    ) * HH + h + 8) * WW + w] = vu.x;
        E[((n * EOUT + ch0 + 2*qp + 1) * HH + h + 8) * WW + w] = vu.y;
    }
}

// ---------------------------------------------------------------------------
// Fused softmax + reassembly + pixel-shuffle + bias (proven R5-measured
// structure: 4 channels/stage, double-buffered).  ONE change: grid.y 2 -> 4
// (64 channels per block, 16 iterations) to halve the straggler tail at the
// reg-limited ~2.6 blocks/SM occupancy.
// ---------------------------------------------------------------------------
__global__ void __launch_bounds__(256) carafe_kernel(
        const float* __restrict__ E, const float* __restrict__ Z,
        const float* __restrict__ bout, float* __restrict__ out) {
    __shared__ float sZ[2][4 * 5 * 72];

    const int nh = blockIdx.x;
    const int n  = nh >> 6;
    const int h  = nh & 63;
    const int cquart = blockIdx.y;      // 0..3  (64 channels each)
    const int tid   = threadIdx.x;
    const int w     = tid & 63;
    const int psel  = (tid >> 6) & 1;
    const int cslot = tid >> 7;

    const int p0 = 2 * psel;
    float kr[50];
    const float* eb = E + (size_t)n * EOUT * HW + h * WW + w;
#pragma unroll
    for (int k = 0; k < 25; k++) {
        kr[k * 2 + 0] = eb[(k * 4 + p0 + 0) * HW];
        kr[k * 2 + 1] = eb[(k * 4 + p0 + 1) * HW];
    }
#pragma unroll
    for (int pp = 0; pp < 2; pp++) {
        float mx = kr[pp];
#pragma unroll
        for (int k = 1; k < 25; k++) mx = fmaxf(mx, kr[k * 2 + pp]);
        float s = 0.0f;
#pragma unroll
        for (int k = 0; k < 25; k++) {
            float ex = __expf(kr[k * 2 + pp] - mx);
            kr[k * 2 + pp] = ex;
            s += ex;
        }
        float inv = 1.0f / s;
#pragma unroll
        for (int k = 0; k < 25; k++) kr[k * 2 + pp] *= inv;
    }

    const int lane64 = tid & 63;
    const int sch    = tid >> 6;
    const int hch    = tid >> 5;
    const int t2     = tid & 31;
    float2* op = (float2*)out;

    auto stage = [&](int it, int buf) {
        const int cbase = cquart * 64 + it * 4;
        float4* sZ4 = (float4*)sZ[buf];
        const float4* zc = (const float4*)(Z +
            ((size_t)(n * OUTC + cbase + sch) * HH) * WW);
        int r = lane64 >> 4, g = lane64 & 15;
        int row = h - 2 + r;
        float4 v = make_float4(0.f, 0.f, 0.f, 0.f);
        if ((unsigned)row < HH) v = zc[row * 16 + g];
        sZ4[sch * 90 + r * 18 + 1 + g] = v;
        if (lane64 < 16) {
            int row2 = h + 2;
            float4 v2 = make_float4(0.f, 0.f, 0.f, 0.f);
            if ((unsigned)row2 < HH) v2 = zc[row2 * 16 + lane64];
            sZ4[sch * 90 + 4 * 18 + 1 + lane64] = v2;
        }
        if (tid < 128 && t2 < 20) {
            int rr = t2 >> 2, cc = t2 & 3;
            int hrow = h - 2 + rr;
            int wc = (cc < 2) ? cc - 2 : 62 + cc;
            float hv = 0.0f;
            if ((unsigned)hrow < HH && (unsigned)wc < WW)
                hv = Z[((size_t)(n * OUTC + cbase + hch) * HH + hrow) * WW + wc];
            sZ[buf][hch * 360 + rr * 72 + ((cc < 2) ? cc + 2 : 66 + cc)] = hv;
        }
    };

    stage(0, 0);
    __syncthreads();

    for (int it = 0; it < 16; it++) {
        if (it < 15) stage(it + 1, (it + 1) & 1);

        const int cbase = cquart * 64 + it * 4;
        const int c0 = cbase + 2 * cslot;
        const float* zb = sZ[it & 1] + (2 * cslot) * 360 + (w + 2);
        float a00 = 0.f, a01 = 0.f, a10 = 0.f, a11 = 0.f;
#pragma unroll
        for (int ki = 0; ki < 5; ki++) {
#pragma unroll
            for (int kj = 0; kj < 5; kj++) {
                int kk = ki * 5 + kj;
                float z0 = zb[ki * 72 + kj];
                float z1 = zb[360 + ki * 72 + kj];
                a00 += z0 * kr[kk * 2 + 0];
                a01 += z0 * kr[kk * 2 + 1];
                a10 += z1 * kr[kk * 2 + 0];
                a11 += z1 * kr[kk * 2 + 1];
            }
        }
        float b0 = __ldg(bout + c0), b1 = __ldg(bout + c0 + 1);
        int row = 2 * h + psel;
        op[((n * OUTC + c0    ) * 128 + row) * 64 + w] = make_float2(a00 + b0, a01 + b0);
        op[((n * OUTC + c0 + 1) * 128 + row) * 64 + w] = make_float2(a10 + b1, a11 + b1);
        __syncthreads();
    }
}

// ---------------------------------------------------------------------------
extern "C" void kernel_launch(void* const* d_in, const int* in_sizes, int n_in,
                              void* d_out, int out_size) {
    const float* x  = (const float*)d_in[0];
    const float* Wd = (const float*)d_in[1];
    const float* bd = (const float*)d_in[2];
    const float* We = (const float*)d_in[3];
    const float* be = (const float*)d_in[4];
    const float* Wo = (const float*)d_in[5];
    const float* bo = (const float*)d_in[6];
    float* out = (float*)d_out;

    static float* gt = nullptr;
    static float* ge = nullptr;
    static float* gz = nullptr;
    static cudaStream_t s2;
    static cudaEvent_t ev_fork, ev_join;
    if (!gt) {
        cudaGetSymbolAddress((void**)&gt, g_t);
        cudaGetSymbolAddress((void**)&ge, g_e);
        cudaGetSymbolAddress((void**)&gz, g_z);
        cudaStreamCreateWithFlags(&s2, cudaStreamNonBlocking);
        cudaEventCreateWithFlags(&ev_fork, cudaEventDisableTiming);
        cudaEventCreateWithFlags(&ev_join, cudaEventDisableTiming);
    }

    // Fork: z = W_out @ x is independent of the t/e path -> run concurrently.
    cudaEventRecord(ev_fork, 0);
    cudaStreamWaitEvent(s2, ev_fork, 0);
    gemm1x1_v<16><<<dim3(16, 16), 256, 0, s2>>>(x, Wo, nullptr, gz, CIN, OUTC);
    cudaEventRecord(ev_join, s2);

    // Main path: t = W_down @ x + b ; e = conv3x3(t) + b
    gemm1x1_v<8><<<dim3(16, 8), 256>>>(x, Wd, bd, gt, CIN, CM);
    enc_conv_kernel<<<dim3(2, 16, 5), 256>>>(gt, We, be, ge);

    // Join, then fused reassembly.
    cudaStreamWaitEvent(0, ev_join, 0);
    carafe_kernel<<<dim3(256, 4), 256>>>(ge, gz, bo, out);
}